// round 17
// baseline (speedup 1.0000x reference)
#include <cuda_runtime.h>
#include <cuda_fp16.h>
#include <cstdint>

// FoldTemporalConvTranspose1d via fp16 mma.sync HMMA GEMM.
//   y[b,co,l] = bias[co] + sum_{k=0..7} sum_c W[k*512+co,c] * x[b,c,l-k]
// R16: 64x64 warp tile (CTA 128co x 256l, 8 warps) halves LDSM bytes per
// MMA (0.375 -> 0.25 LDSM.x4/MMA) to test the LDSM<->HMMA throughput
// coupling indicated by R14/R15 profiles (tensor pinned 65%, L1 54%).

#define CIN   512
#define COUT  512
#define LLEN  2048
#define BATCH 8
#define KW    8
#define TM    128
#define TN    256
#define KC    64
#define NCHUNK (CIN / KC)   // 8
#define NIT   (NCHUNK * KW) // 64
#define SR    264           // strip rows (TN + 8)
#define PS    72            // strip smem row stride (fp16 units, 144 B)
#define NTHREADS 256

#define TILE_ELE   (128 * 64)        // one W tile (co x c), fp16
#define TILE_BYTES (TILE_ELE * 2)    // 16384
#define NSTAGE_W   4

// smem layout (bytes, dynamic)
#define SM_MBAR 0                    // 4 mbarriers (32 B)
#define SW_BASE 1024                 // W stages: 4 x 16384 = 65536
#define SB_BASE (SW_BASE + NSTAGE_W * TILE_BYTES)   // 66560
#define SB_ONE  38016                // one strip: 264 * 72 * 2
#define SMEM_TOTAL (SB_BASE + 2 * SB_ONE)           // 142592 -> occ 1

// ---------------- scratch (static device globals; allocation-free) ----------
__device__ __align__(16) __half g_Wt[NCHUNK * KW * 4 * TILE_ELE];   // 4 MB
__device__ __align__(16) __half g_xf[BATCH * LLEN * CIN];           // 16 MB [b][l][c]

// ---------------- helpers ----------------------------------------------------
__device__ __forceinline__ uint32_t smem_u32(const void* p) {
    uint32_t a;
    asm("{ .reg .u64 t; cvta.to.shared.u64 t, %1; cvt.u32.u64 %0, t; }"
        : "=r"(a) : "l"(p));
    return a;
}
__device__ __forceinline__ void ldmatrix_x4(uint32_t* r, uint32_t addr) {
    asm volatile("ldmatrix.sync.aligned.m8n8.x4.shared.b16 {%0,%1,%2,%3}, [%4];"
                 : "=r"(r[0]), "=r"(r[1]), "=r"(r[2]), "=r"(r[3]) : "r"(addr));
}
__device__ __forceinline__ void mma16816(float* d, const uint32_t* a,
                                         uint32_t b0, uint32_t b1) {
    asm volatile(
        "mma.sync.aligned.m16n8k16.row.col.f32.f16.f16.f32 "
        "{%0,%1,%2,%3}, {%4,%5,%6,%7}, {%8,%9}, {%0,%1,%2,%3};"
        : "+f"(d[0]), "+f"(d[1]), "+f"(d[2]), "+f"(d[3])
        : "r"(a[0]), "r"(a[1]), "r"(a[2]), "r"(a[3]), "r"(b0), "r"(b1));
}
__device__ __forceinline__ void cpa16z(uint32_t dst, const void* src, bool p) {
    int sz = p ? 16 : 0;
    asm volatile(
        "{ .reg .u64 g; cvta.to.global.u64 g, %1;"
        " cp.async.cg.shared.global [%0], [g], 16, %2; }"
        :: "r"(dst), "l"(src), "r"(sz) : "memory");
}
__device__ __forceinline__ void cpa_commit() {
    asm volatile("cp.async.commit_group;" ::: "memory");
}
template <int N>
__device__ __forceinline__ void cpa_wait() {
    asm volatile("cp.async.wait_group %0;" :: "n"(N) : "memory");
}
__device__ __forceinline__ void bulk_ld(uint32_t dst, const void* src,
                                        uint32_t bytes, uint32_t mbar) {
    asm volatile(
        "{ .reg .u64 g; cvta.to.global.u64 g, %1;"
        " cp.async.bulk.shared::cluster.global.mbarrier::complete_tx::bytes"
        " [%0], [g], %2, [%3]; }"
        :: "r"(dst), "l"(src), "r"(bytes), "r"(mbar) : "memory");
}
#define MBAR_INIT(a, c) \
    asm volatile("mbarrier.init.shared.b64 [%0], %1;" :: "r"(a), "r"(c) : "memory")
#define MBAR_EXPECT_TX(a, n) \
    asm volatile("mbarrier.arrive.expect_tx.shared.b64 _, [%0], %1;" \
                 :: "r"(a), "r"(n) : "memory")
#define MBAR_WAIT(a, ph) do {                                                     \
    uint32_t _m = (a), _p = (ph), _d;                                             \
    asm volatile("{ .reg .pred p;"                                                \
        "mbarrier.try_wait.parity.acquire.cta.shared::cta.b64 p, [%1], %2;"       \
        "selp.b32 %0,1,0,p; }" : "=r"(_d) : "r"(_m), "r"(_p) : "memory");         \
    if (!_d) {                                                                    \
        asm volatile("{ .reg .pred P1; WL_%=:"                                    \
            "mbarrier.try_wait.parity.acquire.cta.shared::cta.b64 P1, [%0], %1, 0x989680;" \
            "@P1 bra.uni WD_%=; bra.uni WL_%=; WD_%=: }"                          \
            :: "r"(_m), "r"(_p) : "memory");                                      \
    }                                                                             \
} while (0)

__device__ __forceinline__ uint32_t pack2h(__half a, __half b) {
    uint16_t ua = *reinterpret_cast<uint16_t*>(&a);
    uint16_t ub = *reinterpret_cast<uint16_t*>(&b);
    return (uint32_t)ua | ((uint32_t)ub << 16);
}

// ---------------- fused pre-pass: W tiling + x transpose ----------------------
#define WBLOCKS 1024
__global__ __launch_bounds__(256)
void convert_fused(const float* __restrict__ W, const float* __restrict__ x) {
    if (blockIdx.x < WBLOCKS) {
        int idx = blockIdx.x * 256 + threadIdx.x;        // 16B chunks (8 fp16)
        int rowg = idx >> 6;                              // W row (tap*512+co)
        int c8   = (idx & 63) * 8;                        // c start
        const float* src = W + (size_t)rowg * CIN + c8;
        float4 v0 = reinterpret_cast<const float4*>(src)[0];
        float4 v1 = reinterpret_cast<const float4*>(src)[1];
        uint4 o;
        o.x = pack2h(__float2half_rn(v0.x), __float2half_rn(v0.y));
        o.y = pack2h(__float2half_rn(v0.z), __float2half_rn(v0.w));
        o.z = pack2h(__float2half_rn(v1.x), __float2half_rn(v1.y));
        o.w = pack2h(__float2half_rn(v1.z), __float2half_rn(v1.w));

        int tap = rowg >> 9;
        int co  = rowg & 511;
        int cy  = co >> 7;
        int r   = co & 127;
        int ci  = c8 >> 6;
        int cc  = c8 & 63;
        size_t dst = (size_t)(((ci * KW + tap) * 4 + cy)) * TILE_ELE
                     + r * 64 + (cc ^ ((r & 7) << 3));
        *reinterpret_cast<uint4*>(g_Wt + dst) = o;
    } else {
        __shared__ float t[32][33];
        int i = blockIdx.x - WBLOCKS;          // 0 .. 8191
        const int b  = i >> 10;
        const int rem = i & 1023;
        const int cbase = (rem >> 6) * 32;
        const int lbase = (rem & 63) * 32;
        const int tx = threadIdx.x & 31;
        const int ty = threadIdx.x >> 5;
#pragma unroll
        for (int r = 0; r < 4; ++r) {
            int c = cbase + ty + r * 8;
            t[ty + r * 8][tx] = x[((size_t)b * CIN + c) * LLEN + lbase + tx];
        }
        __syncthreads();
#pragma unroll
        for (int r = 0; r < 4; ++r) {
            int l = lbase + ty + r * 8;
            float v = t[tx][ty + r * 8];
            g_xf[((size_t)b * LLEN + l) * CIN + cbase + tx] = __float2half_rn(v);
        }
    }
}

// ---------------- main GEMM ---------------------------------------------------
__global__ __launch_bounds__(NTHREADS, 1)
void fold_convT_mma(const float* __restrict__ bias, float* __restrict__ out)
{
    extern __shared__ char smem[];
    const uint32_t sbase = smem_u32(smem);

    const int tid  = threadIdx.x;
    const int lane = tid & 31;
    const int wid  = tid >> 5;           // 0..7
    const int wm   = wid >> 2;           // 0..1 -> co 64-block
    const int wn   = wid & 3;            // 0..3 -> l 64-block
    const int bb   = blockIdx.z;
    const int co0  = blockIdx.y * TM;
    const int cy   = blockIdx.y;
    const int l0   = blockIdx.x * TN;

    float acc[4][8][4];                  // mf x nf(8 of n8) x regs
#pragma unroll
    for (int i = 0; i < 4; ++i)
#pragma unroll
        for (int j = 0; j < 8; ++j)
#pragma unroll
            for (int q = 0; q < 4; ++q) acc[i][j][q] = 0.0f;

    // A addressing inside swizzled W tile
    const int arow_l = wm * 64 + (lane & 15);
    const int a_sv   = (arow_l & 7) << 3;
    const int a_colb = (lane >> 4) * 8;
    // B (strip) ldmatrix lane offset
    const int b_lane = ((lane & 7) + ((lane >> 4) << 3)) * PS + ((lane >> 3) & 1) * 8;

    const uint32_t mb = sbase + SM_MBAR;     // 4 mbarriers, 8 B apart

    if (tid == 0) {
#pragma unroll
        for (int s = 0; s < NSTAGE_W; ++s) MBAR_INIT(mb + s * 8, 1);
    }
    __syncthreads();

    auto issue_Wbulk = [&](int it) {
        const int st = it & 3;
        const __half* src = g_Wt + (size_t)(it * 4 + cy) * TILE_ELE;
        MBAR_EXPECT_TX(mb + st * 8, TILE_BYTES);
        bulk_ld(sbase + SW_BASE + st * TILE_BYTES, src, TILE_BYTES, mb + st * 8);
    };
    auto issue_strip = [&](int ci, int stage) {
        const int c0 = ci * KC;
#pragma unroll
        for (int e = tid; e < SR * 8; e += NTHREADS) {
            int s = e >> 3;
            int q = (e & 7) * 8;
            int l = l0 + s - 7;
            bool p = (l >= 0) && (l < LLEN);
            int lc = p ? l : 0;
            size_t o = ((size_t)bb * LLEN + lc) * CIN + c0 + q;
            cpa16z(sbase + SB_BASE + stage * SB_ONE + (s * PS + q) * 2,
                   g_xf + o, p);
        }
    };

    // ---- prologue: strip(0) + W(0..2) ----
    issue_strip(0, 0);
    cpa_commit();
    if (tid == 0) { issue_Wbulk(0); issue_Wbulk(1); issue_Wbulk(2); }

    uint32_t wph[NSTAGE_W] = {0, 0, 0, 0};

#pragma unroll 1
    for (int it = 0; it < NIT; ++it) {
        const int ci  = it >> 3;
        const int tap = it & 7;
        const int st  = it & 3;

        if (tap == 0) cpa_wait<0>();   // strip(ci) present (own thread)
        __syncthreads();               // all warps done compute(it-1)

        if (tid == 0 && it + 3 < NIT) issue_Wbulk(it + 3);
        if (tap == 4 && it + 4 < NIT) {        // prefetch next strip: 3-it slack
            issue_strip(ci + 1, (ci + 1) & 1);
            cpa_commit();
        }

        MBAR_WAIT(mb + st * 8, wph[st]);       // W tile(it); issued at it-3
        wph[st] ^= 1;

        const uint32_t sA_u = sbase + SW_BASE + st * TILE_BYTES;
        const uint32_t sB_u = sbase + SB_BASE + (ci & 1) * SB_ONE;
        const int rowOff = (wn * 64 + 7 - tap) * PS;

#pragma unroll
        for (int ks = 0; ks < 4; ++ks) {
            uint32_t B[16];
#pragma unroll
            for (int nfp = 0; nfp < 4; ++nfp) {
                uint32_t eb = (uint32_t)(b_lane + rowOff + nfp * 16 * PS
                                         + ks * 16) * 2;
                ldmatrix_x4(&B[nfp * 4], sB_u + eb);
            }

            uint32_t a[4][4];
            const int colsw = (a_colb + ks * 16) ^ a_sv;
#pragma unroll
            for (int mf = 0; mf < 4; ++mf) {
                uint32_t ab = (uint32_t)((arow_l + mf * 16) * 64 + colsw) * 2;
                ldmatrix_x4(a[mf], sA_u + ab);
            }

#pragma unroll
            for (int mf = 0; mf < 4; ++mf)
#pragma unroll
                for (int nf = 0; nf < 8; ++nf)
                    mma16816(acc[mf][nf], a[mf], B[nf * 2], B[nf * 2 + 1]);
        }
    }

    // ---- epilogue: add bias, store float2 per (row, 8-col frag) ----
    const int r  = lane >> 2;
    const int cq = (lane & 3) * 2;
#pragma unroll
    for (int mf = 0; mf < 4; ++mf) {
#pragma unroll
        for (int h2 = 0; h2 < 2; ++h2) {
            int row = co0 + wm * 64 + mf * 16 + h2 * 8 + r;
            float bv = __ldg(bias + row);
            float* orow = out + ((size_t)bb * COUT + row) * LLEN
                          + l0 + wn * 64 + cq;
#pragma unroll
            for (int nf = 0; nf < 8; ++nf) {
                float2 v;
                v.x = acc[mf][nf][h2 * 2 + 0] + bv;
                v.y = acc[mf][nf][h2 * 2 + 1] + bv;
                *reinterpret_cast<float2*>(orow + nf * 8) = v;
            }
        }
    }
}

extern "C" void kernel_launch(void* const* d_in, const int* in_sizes, int n_in,
                              void* d_out, int out_size) {
    const float* x    = (const float*)d_in[0];   // [8, 512, 2048]
    const float* W    = (const float*)d_in[1];   // [4096, 512]
    const float* bias = (const float*)d_in[2];   // [512]
    float* out        = (float*)d_out;           // [8, 512, 2048]

    convert_fused<<<WBLOCKS + (LLEN / 32) * (CIN / 32) * BATCH, 256>>>(W, x);

    cudaFuncSetAttribute(fold_convT_mma,
                         cudaFuncAttributeMaxDynamicSharedMemorySize, SMEM_TOTAL);
    dim3 grid(LLEN / TN, COUT / TM, BATCH);      // (8, 4, 8) = 256 CTAs
    fold_convT_mma<<<grid, NTHREADS, SMEM_TOTAL>>>(bias, out);
}